// round 7
// baseline (speedup 1.0000x reference)
#include <cuda_runtime.h>
#include <math.h>

#define T 20
#define NC 80
#define BS 32

__constant__ float c_anch[3][3][2] = {
    {{116.f, 90.f}, {156.f, 198.f}, {373.f, 326.f}},
    {{ 30.f, 61.f}, { 62.f,  45.f}, { 59.f, 119.f}},
    {{ 10.f, 13.f}, { 16.f,  30.f}, { 33.f,  23.f}}
};

__device__ __forceinline__ float tanh_ap(float x) {
    float r; asm("tanh.approx.f32 %0, %1;" : "=f"(r) : "f"(x)); return r;
}
// stable softplus, fast intrinsics
__device__ __forceinline__ float sp(float z) {
    return fmaxf(z, 0.f) + __logf(1.f + __expf(-fabsf(z)));
}

struct SMem {
    float4 box[T];     // target box, grid units (degenerate if invalid)
    float4 tgt[T];     // tx,ty,tw,th
    float  aeps[T];    // area + 1e-16
    int    flat[T];    // -1 if invalid
    int    lab[T];
    int    pos[256];   // winning target per block-local cell
    float  wred[8];
};

template<int LVL, int W, int HW>
__device__ __forceinline__ void level_body(
    SMem& sm, int nblk, int b,
    const float* __restrict__ x,
    const float* __restrict__ gtb,
    const int*   __restrict__ gtl,
    float* __restrict__ out)
{
    constexpr int   N      = 3 * HW;
    constexpr float stride = (LVL == 0) ? 32.f : (LVL == 1) ? 16.f : 8.f;
    constexpr float inv_s  = 1.f / stride;
    const int tid  = threadIdx.x;
    const int lane = tid & 31;
    const int wrp  = tid >> 5;

    float sax[3], say[3];
#pragma unroll
    for (int a = 0; a < 3; a++) {
        sax[a] = c_anch[LVL][a][0] * inv_s;
        say[a] = c_anch[LVL][a][1] * inv_s;
    }

    const int base = nblk * 256;
    const int n    = base + tid;
    const bool act = (n < N);

    // ---- issue the 5 global loads ASAP (before any barrier) ----
    int aa  = n / HW;                   // compile-time magic div
    int rem = n - aa * HW;
    int jj  = rem / W;
    int ii  = rem - jj * W;
    const int off = aa * (85 * HW) + rem;
    const size_t base_b = (size_t)b * 255 * HW;

    float zx = 0.f, zy = 0.f, zw = 0.f, zh = 0.f, zc = 0.f;
    if (act) {
        const float* xp = x + base_b + off;
        zx = xp[0]; zy = xp[HW]; zw = xp[2*HW]; zh = xp[3*HW]; zc = xp[4*HW];
    }

    // ---- phase A: init pos table + per-target precompute ----
    sm.pos[tid] = -1;
    if (tid < T) {
        const float* g = gtb + ((size_t)b * T + tid) * 4;
        float a1 = g[0], b1 = g[1], a2 = g[2], b2 = g[3];
        bool valid = (a1 != -1.f) || (b1 != -1.f) || (a2 != -1.f) || (b2 != -1.f);

        float tbx1 = a1 * inv_s, tby1 = b1 * inv_s;
        float tbx2 = a2 * inv_s, tby2 = b2 * inv_s;
        if (!valid) { tbx1 = tby1 = tbx2 = tby2 = 0.f; }
        sm.box[tid]  = make_float4(tbx1, tby1, tbx2, tby2);
        sm.aeps[tid] = (tbx2 - tbx1) * (tby2 - tby1) + 1e-16f;

        float gw  = (a2 - a1) * inv_s;
        float gh  = (b2 - b1) * inv_s;
        float gxc = (a1 + a2) * (0.5f * inv_s);
        float gyc = (b1 + b2) * (0.5f * inv_s);
        int gi = min(max((int)gxc, 0), W - 1);
        int gj = min(max((int)gyc, 0), W - 1);

        int best = 0; float bi = -1.f;
#pragma unroll
        for (int a = 0; a < 3; a++) {
            float inter = fminf(gw, sax[a]) * fminf(gh, say[a]);
            float u = gw * gh + sax[a] * say[a] - inter + 1e-16f;
            float io = inter / u;
            if (io > bi) { bi = io; best = a; }
        }
        sm.flat[tid] = valid ? (best * HW + gj * W + gi) : -1;
        float bsx = (best == 0) ? sax[0] : (best == 1) ? sax[1] : sax[2];
        float bsy = (best == 0) ? say[0] : (best == 1) ? say[1] : say[2];
        sm.tgt[tid] = make_float4(gxc - (float)gi, gyc - (float)gj,
                                  logf(gw / bsx + 1e-16f),
                                  logf(gh / bsy + 1e-16f));
        sm.lab[tid] = min(max(gtl[b * T + tid], 0), NC - 1);
    }
    __syncthreads();

    // ---- phase B: scatter winners (last-writer == max t) ----
    if (tid < T) {
        int f = sm.flat[tid];
        int loc = f - base;
        if (f >= 0 && loc >= 0 && loc < 256) atomicMax(&sm.pos[loc], tid);
    }
    __syncthreads();

    const int Lp = sm.pos[tid];

    // ---- decode ----
    float sxo = 0.5f * tanh_ap(0.5f * zx) + 0.5f;   // sigmoid (threshold-only)
    float syo = 0.5f * tanh_ap(0.5f * zy) + 0.5f;
    float cx = sxo + (float)ii;
    float cy = syo + (float)jj;
    float sxa = (aa == 0) ? sax[0] : (aa == 1) ? sax[1] : sax[2];
    float sya = (aa == 0) ? say[0] : (aa == 1) ? say[1] : say[2];
    float bw = __expf(zw) * sxa;
    float bh = __expf(zh) * sya;
    float px1 = cx - 0.5f * bw, py1 = cy - 0.5f * bh;
    float px2 = cx + 0.5f * bw, py2 = cy + 0.5f * bh;
    float ap  = bw * bh;
    if (!act) { px1 = py1 = 1e30f; px2 = py2 = -1e30f; ap = 1e30f; }

    // ---- ignore loop (fma-folded compare) ----
    int Lig = -1;
#pragma unroll
    for (int t = 0; t < T; t++) {
        float4 bb = sm.box[t];
        float rhs = sm.aeps[t];
        float iw = fminf(px2, bb.z) - fmaxf(px1, bb.x);
        float ih = fminf(py2, bb.w) - fmaxf(py1, bb.y);
        float in_ = fmaxf(iw, 0.f) * fmaxf(ih, 0.f);
        if (fmaf(3.f, in_, -ap) > rhs) Lig = t;
    }

    const bool pos = act && (Lp >= 0) && (Lp >= Lig);
    const bool neg = act && (Lig < 0) && !pos;

    // ---- loss assembly ----
    float loss = 0.f;
    if (neg) loss = sp(zc);                   // negative conf, target 0

    unsigned m0 = 0, m1 = 0, m2 = 0;
    if (pos) {
        float4 tg = sm.tgt[Lp];
        float bxl = tg.x * sp(-zx) + (1.f - tg.x) * sp(zx);
        float byl = tg.y * sp(-zy) + (1.f - tg.y) * sp(zy);
        float dw = zw - tg.z, dh = zh - tg.w;
        loss = 2.5f * (bxl + byl + dw * dw + dh * dh) + sp(-zc);
#pragma unroll
        for (int t = 0; t < T; t++)
            if (sm.flat[t] == n) {
                int l = sm.lab[t];
                if (l < 32)      m0 |= 1u << l;
                else if (l < 64) m1 |= 1u << (l - 32);
                else             m2 |= 1u << (l - 64);
            }
    }

    // ---- warp-cooperative class loss (rare positives) ----
    // BCE(sig(z),1) = sp(z) - z ; BCE(sig(z),0) = sp(z)
    unsigned bal = __ballot_sync(0xffffffffu, pos);
    while (bal) {
        int src = __ffs(bal) - 1;
        bal &= bal - 1;
        int offs    = __shfl_sync(0xffffffffu, off, src);
        unsigned M0 = __shfl_sync(0xffffffffu, m0, src);
        unsigned M1 = __shfl_sync(0xffffffffu, m1, src);
        unsigned M2 = __shfl_sync(0xffffffffu, m2, src);
        const float* cps = x + base_b + offs + (size_t)5 * HW;
        float z = __ldg(cps + (size_t)lane * HW);
        float acc = sp(z) - (((M0 >> lane) & 1u) ? z : 0.f);
        z = __ldg(cps + (size_t)(lane + 32) * HW);
        acc += sp(z) - (((M1 >> lane) & 1u) ? z : 0.f);
        if (lane < 16) {
            z = __ldg(cps + (size_t)(lane + 64) * HW);
            acc += sp(z) - (((M2 >> lane) & 1u) ? z : 0.f);
        }
        loss += acc;
    }

    // ---- reduction ----
#pragma unroll
    for (int o = 16; o > 0; o >>= 1)
        loss += __shfl_down_sync(0xffffffffu, loss, o);
    if (lane == 0) sm.wred[wrp] = loss;
    __syncthreads();
    if (wrp == 0) {
        float v = (lane < 8) ? sm.wred[lane] : 0.f;
#pragma unroll
        for (int o = 4; o > 0; o >>= 1)
            v += __shfl_down_sync(0xffffffffu, v, o);
        if (lane == 0) atomicAdd(out, v * (1.f / (float)BS));
    }
}

// grid: (42, 32). bx in [0,2) -> lvl0; [2,10) -> lvl1; [10,42) -> lvl2.
// 256 threads x 1 cell = 256 cells/block -> high occupancy for latency hiding.
__global__ __launch_bounds__(256, 6)
void yolo_loss_kernel(const float* __restrict__ x0,
                      const float* __restrict__ x1,
                      const float* __restrict__ x2,
                      const float* __restrict__ gtb,
                      const int*   __restrict__ gtl,
                      float* __restrict__ out)
{
    __shared__ SMem sm;
    const int bx = blockIdx.x;
    const int b  = blockIdx.y;
    if (bx < 2)       level_body<0, 13, 169 >(sm, bx,      b, x0, gtb, gtl, out);
    else if (bx < 10) level_body<1, 26, 676 >(sm, bx - 2,  b, x1, gtb, gtl, out);
    else              level_body<2, 52, 2704>(sm, bx - 10, b, x2, gtb, gtl, out);
}

extern "C" void kernel_launch(void* const* d_in, const int* in_sizes, int n_in,
                              void* d_out, int out_size)
{
    const float* x0  = (const float*)d_in[0];
    const float* x1  = (const float*)d_in[1];
    const float* x2  = (const float*)d_in[2];
    const float* gtb = (const float*)d_in[3];
    const int*   gtl = (const int*)  d_in[4];
    float* out = (float*)d_out;

    cudaMemsetAsync(out, 0, sizeof(float));
    dim3 grid(42, BS);
    yolo_loss_kernel<<<grid, 256>>>(x0, x1, x2, gtb, gtl, out);
}

// round 8
// speedup vs baseline: 1.0741x; 1.0741x over previous
#include <cuda_runtime.h>
#include <math.h>

#define T 20
#define NC 80
#define BS 32

__constant__ float c_anch[3][3][2] = {
    {{116.f, 90.f}, {156.f, 198.f}, {373.f, 326.f}},
    {{ 30.f, 61.f}, { 62.f,  45.f}, { 59.f, 119.f}},
    {{ 10.f, 13.f}, { 16.f,  30.f}, { 33.f,  23.f}}
};

__device__ __forceinline__ float tanh_ap(float x) {
    float r; asm("tanh.approx.f32 %0, %1;" : "=f"(r) : "f"(x)); return r;
}
// stable softplus, fast intrinsics
__device__ __forceinline__ float sp(float z) {
    return fmaxf(z, 0.f) + __logf(1.f + __expf(-fabsf(z)));
}

struct SMem {
    float4 box[T];     // target box, grid units (degenerate if invalid)
    float4 tgt[T];     // tx,ty,tw,th
    float  aeps[T];    // area + 1e-16
    int    flat[T];    // -1 if invalid
    int    lab[T];
    int    pos[512];   // winning target per block-local cell
    float  wred[8];
};

// Warp-parallel target screen: which targets' boxes overlap this warp's
// cell window [imin,imax+1]x[jmin,jmax+1]? (necessary condition for IoU>0.5)
__device__ __forceinline__ unsigned screen_targets(
    const SMem& sm, int lane, int ii, int jj)
{
    int imin = __reduce_min_sync(0xffffffffu, ii);
    int imax = __reduce_max_sync(0xffffffffu, ii);
    int jmin = __reduce_min_sync(0xffffffffu, jj);
    int jmax = __reduce_max_sync(0xffffffffu, jj);
    float4 tb = sm.box[lane < T ? lane : 0];
    bool ov = (lane < T)
           && (tb.x <= (float)(imax + 1)) && (tb.z >= (float)imin)
           && (tb.y <= (float)(jmax + 1)) && (tb.w >= (float)jmin);
    return __ballot_sync(0xffffffffu, ov);
}

template<int LVL, int W, int HW>
__device__ __forceinline__ void level_body(
    SMem& sm, int nblk, int b,
    const float* __restrict__ x,
    const float* __restrict__ gtb,
    const int*   __restrict__ gtl,
    float* __restrict__ out)
{
    constexpr int   N      = 3 * HW;
    constexpr float stride = (LVL == 0) ? 32.f : (LVL == 1) ? 16.f : 8.f;
    constexpr float inv_s  = 1.f / stride;
    const int tid  = threadIdx.x;
    const int lane = tid & 31;
    const int wrp  = tid >> 5;

    float sax[3], say[3];
#pragma unroll
    for (int a = 0; a < 3; a++) {
        sax[a] = c_anch[LVL][a][0] * inv_s;
        say[a] = c_anch[LVL][a][1] * inv_s;
    }

    const int base = nblk * 512;
    const int n0 = base + tid;
    const int n1 = base + 256 + tid;
    const bool act0 = (n0 < N);
    const bool act1 = (n1 < N);
    const int ncl0 = act0 ? n0 : (N - 1);   // clamped for tight windows
    const int ncl1 = act1 ? n1 : (N - 1);

    // ---- addressing (compile-time magic div) + early global loads ----
    int a0   = ncl0 / HW;
    int rem0 = ncl0 - a0 * HW;
    int j0   = rem0 / W;
    int i0   = rem0 - j0 * W;
    const int off0 = a0 * (85 * HW) + rem0;
    int a1   = ncl1 / HW;
    int rem1 = ncl1 - a1 * HW;
    int j1   = rem1 / W;
    int i1   = rem1 - j1 * W;
    const int off1 = a1 * (85 * HW) + rem1;
    const size_t base_b = (size_t)b * 255 * HW;

    float zx0=0,zy0=0,zw0=0,zh0=0,zc0=0, zx1=0,zy1=0,zw1=0,zh1=0,zc1=0;
    if (act0) {
        const float* xp = x + base_b + off0;
        zx0 = xp[0]; zy0 = xp[HW]; zw0 = xp[2*HW]; zh0 = xp[3*HW]; zc0 = xp[4*HW];
    }
    if (act1) {
        const float* xp = x + base_b + off1;
        zx1 = xp[0]; zy1 = xp[HW]; zw1 = xp[2*HW]; zh1 = xp[3*HW]; zc1 = xp[4*HW];
    }

    // ---- phase A: init pos table + per-target precompute ----
    sm.pos[tid]       = -1;
    sm.pos[tid + 256] = -1;
    if (tid < T) {
        const float* g = gtb + ((size_t)b * T + tid) * 4;
        float ax1 = g[0], ay1 = g[1], ax2 = g[2], ay2 = g[3];
        bool valid = (ax1 != -1.f) || (ay1 != -1.f) || (ax2 != -1.f) || (ay2 != -1.f);

        float tbx1 = ax1 * inv_s, tby1 = ay1 * inv_s;
        float tbx2 = ax2 * inv_s, tby2 = ay2 * inv_s;
        if (!valid) { tbx1 = tby1 = tbx2 = tby2 = -1e30f; }  // never overlaps any window
        sm.box[tid]  = make_float4(tbx1, tby1, tbx2, tby2);
        sm.aeps[tid] = (tbx2 - tbx1) * (tby2 - tby1) + 1e-16f;

        float gw  = (ax2 - ax1) * inv_s;
        float gh  = (ay2 - ay1) * inv_s;
        float gxc = (ax1 + ax2) * (0.5f * inv_s);
        float gyc = (ay1 + ay2) * (0.5f * inv_s);
        int gi = min(max((int)gxc, 0), W - 1);
        int gj = min(max((int)gyc, 0), W - 1);

        int best = 0; float bi = -1.f;
#pragma unroll
        for (int a = 0; a < 3; a++) {
            float inter = fminf(gw, sax[a]) * fminf(gh, say[a]);
            float u = gw * gh + sax[a] * say[a] - inter + 1e-16f;
            float io = inter / u;
            if (io > bi) { bi = io; best = a; }
        }
        sm.flat[tid] = valid ? (best * HW + gj * W + gi) : -1;
        float bsx = (best == 0) ? sax[0] : (best == 1) ? sax[1] : sax[2];
        float bsy = (best == 0) ? say[0] : (best == 1) ? say[1] : say[2];
        sm.tgt[tid] = make_float4(gxc - (float)gi, gyc - (float)gj,
                                  logf(gw / bsx + 1e-16f),
                                  logf(gh / bsy + 1e-16f));
        sm.lab[tid] = min(max(gtl[b * T + tid], 0), NC - 1);
    }
    __syncthreads();

    // ---- phase B: scatter winners (last-writer == max t) ----
    if (tid < T) {
        int f = sm.flat[tid];
        int loc = f - base;
        if (f >= 0 && loc >= 0 && loc < 512) atomicMax(&sm.pos[loc], tid);
    }
    __syncthreads();

    const int Lp0 = sm.pos[tid];
    const int Lp1 = sm.pos[tid + 256];

    // ---- warp-parallel screen: which targets can possibly ignore these cells ----
    const unsigned mask0 = screen_targets(sm, lane, i0, j0);
    const unsigned mask1 = screen_targets(sm, lane, i1, j1);

    // ---- decode + pruned ignore loop, cell 0 ----
    int Lig0 = -1, Lig1 = -1;
    if (mask0) {   // warp-uniform branch
        float sx = 0.5f * tanh_ap(0.5f * zx0) + 0.5f;
        float sy = 0.5f * tanh_ap(0.5f * zy0) + 0.5f;
        float cx = sx + (float)i0, cy = sy + (float)j0;
        float sxa = (a0 == 0) ? sax[0] : (a0 == 1) ? sax[1] : sax[2];
        float sya = (a0 == 0) ? say[0] : (a0 == 1) ? say[1] : say[2];
        float bw = __expf(zw0) * sxa, bh = __expf(zh0) * sya;
        float px1 = cx - 0.5f*bw, py1 = cy - 0.5f*bh;
        float px2 = cx + 0.5f*bw, py2 = cy + 0.5f*bh;
        float ap  = act0 ? (bw * bh) : 1e30f;
        unsigned m = mask0;
        while (m) {
            int t = __ffs(m) - 1; m &= m - 1;
            float4 bb = sm.box[t];
            float iw = fminf(px2, bb.z) - fmaxf(px1, bb.x);
            float ih = fminf(py2, bb.w) - fmaxf(py1, bb.y);
            float in_ = fmaxf(iw, 0.f) * fmaxf(ih, 0.f);
            if (fmaf(3.f, in_, -ap) > sm.aeps[t]) Lig0 = t;  // ascending: last = max
        }
    }
    if (mask1) {
        float sx = 0.5f * tanh_ap(0.5f * zx1) + 0.5f;
        float sy = 0.5f * tanh_ap(0.5f * zy1) + 0.5f;
        float cx = sx + (float)i1, cy = sy + (float)j1;
        float sxa = (a1 == 0) ? sax[0] : (a1 == 1) ? sax[1] : sax[2];
        float sya = (a1 == 0) ? say[0] : (a1 == 1) ? say[1] : say[2];
        float bw = __expf(zw1) * sxa, bh = __expf(zh1) * sya;
        float px1 = cx - 0.5f*bw, py1 = cy - 0.5f*bh;
        float px2 = cx + 0.5f*bw, py2 = cy + 0.5f*bh;
        float ap  = act1 ? (bw * bh) : 1e30f;
        unsigned m = mask1;
        while (m) {
            int t = __ffs(m) - 1; m &= m - 1;
            float4 bb = sm.box[t];
            float iw = fminf(px2, bb.z) - fmaxf(px1, bb.x);
            float ih = fminf(py2, bb.w) - fmaxf(py1, bb.y);
            float in_ = fmaxf(iw, 0.f) * fmaxf(ih, 0.f);
            if (fmaf(3.f, in_, -ap) > sm.aeps[t]) Lig1 = t;
        }
    }

    const bool pos0 = act0 && (Lp0 >= 0) && (Lp0 >= Lig0);
    const bool pos1 = act1 && (Lp1 >= 0) && (Lp1 >= Lig1);
    const bool neg0 = act0 && (Lig0 < 0) && !pos0;
    const bool neg1 = act1 && (Lig1 < 0) && !pos1;

    // ---- loss assembly ----
    // batched negative conf: sp(z) = max(z,0) + log1p(e^-|z|); product the log1p args
    float e0 = __expf(-fabsf(zc0));
    float e1 = __expf(-fabsf(zc1));
    float tprod = (neg0 ? (1.f + e0) : 1.f) * (neg1 ? (1.f + e1) : 1.f);
    float bacc  = (neg0 ? fmaxf(zc0, 0.f) : 0.f) + (neg1 ? fmaxf(zc1, 0.f) : 0.f);
    float loss = bacc + __logf(tprod);

    unsigned m0a=0, m1a=0, m2a=0, m0b=0, m1b=0, m2b=0;
    if (pos0) {
        float4 tg = sm.tgt[Lp0];
        float bxl = tg.x * sp(-zx0) + (1.f - tg.x) * sp(zx0);
        float byl = tg.y * sp(-zy0) + (1.f - tg.y) * sp(zy0);
        float dw = zw0 - tg.z, dh = zh0 - tg.w;
        loss += 2.5f * (bxl + byl + dw*dw + dh*dh) + sp(-zc0);
#pragma unroll
        for (int t = 0; t < T; t++)
            if (sm.flat[t] == n0) {
                int l = sm.lab[t];
                if (l < 32) m0a |= 1u << l; else if (l < 64) m1a |= 1u << (l-32); else m2a |= 1u << (l-64);
            }
    }
    if (pos1) {
        float4 tg = sm.tgt[Lp1];
        float bxl = tg.x * sp(-zx1) + (1.f - tg.x) * sp(zx1);
        float byl = tg.y * sp(-zy1) + (1.f - tg.y) * sp(zy1);
        float dw = zw1 - tg.z, dh = zh1 - tg.w;
        loss += 2.5f * (bxl + byl + dw*dw + dh*dh) + sp(-zc1);
#pragma unroll
        for (int t = 0; t < T; t++)
            if (sm.flat[t] == n1) {
                int l = sm.lab[t];
                if (l < 32) m0b |= 1u << l; else if (l < 64) m1b |= 1u << (l-32); else m2b |= 1u << (l-64);
            }
    }

    // ---- warp-cooperative class loss (rare positives) ----
    // BCE(sig(z),1) = sp(z) - z ; BCE(sig(z),0) = sp(z)
#pragma unroll
    for (int c = 0; c < 2; c++) {
        bool p       = c ? pos1 : pos0;
        int  off     = c ? off1 : off0;
        unsigned M0t = c ? m0b : m0a, M1t = c ? m1b : m1a, M2t = c ? m2b : m2a;
        unsigned bal = __ballot_sync(0xffffffffu, p);
        while (bal) {
            int src = __ffs(bal) - 1;
            bal &= bal - 1;
            int offs    = __shfl_sync(0xffffffffu, off, src);
            unsigned M0 = __shfl_sync(0xffffffffu, M0t, src);
            unsigned M1 = __shfl_sync(0xffffffffu, M1t, src);
            unsigned M2 = __shfl_sync(0xffffffffu, M2t, src);
            const float* cps = x + base_b + offs + (size_t)5 * HW;
            float z = __ldg(cps + (size_t)lane * HW);
            float acc = sp(z) - (((M0 >> lane) & 1u) ? z : 0.f);
            z = __ldg(cps + (size_t)(lane + 32) * HW);
            acc += sp(z) - (((M1 >> lane) & 1u) ? z : 0.f);
            if (lane < 16) {
                z = __ldg(cps + (size_t)(lane + 64) * HW);
                acc += sp(z) - (((M2 >> lane) & 1u) ? z : 0.f);
            }
            loss += acc;
        }
    }

    // ---- reduction ----
#pragma unroll
    for (int o = 16; o > 0; o >>= 1)
        loss += __shfl_down_sync(0xffffffffu, loss, o);
    if (lane == 0) sm.wred[wrp] = loss;
    __syncthreads();
    if (wrp == 0) {
        float v = (lane < 8) ? sm.wred[lane] : 0.f;
#pragma unroll
        for (int o = 4; o > 0; o >>= 1)
            v += __shfl_down_sync(0xffffffffu, v, o);
        if (lane == 0) atomicAdd(out, v * (1.f / (float)BS));
    }
}

// grid: (21, 32). bx==0 -> lvl0; [1,5) -> lvl1; [5,21) -> lvl2.
// 256 threads x 2 strided cells = 512 cells/block.
__global__ __launch_bounds__(256)
void yolo_loss_kernel(const float* __restrict__ x0,
                      const float* __restrict__ x1,
                      const float* __restrict__ x2,
                      const float* __restrict__ gtb,
                      const int*   __restrict__ gtl,
                      float* __restrict__ out)
{
    __shared__ SMem sm;
    const int bx = blockIdx.x;
    const int b  = blockIdx.y;
    if (bx == 0)      level_body<0, 13, 169 >(sm, 0,      b, x0, gtb, gtl, out);
    else if (bx < 5)  level_body<1, 26, 676 >(sm, bx - 1, b, x1, gtb, gtl, out);
    else              level_body<2, 52, 2704>(sm, bx - 5, b, x2, gtb, gtl, out);
}

extern "C" void kernel_launch(void* const* d_in, const int* in_sizes, int n_in,
                              void* d_out, int out_size)
{
    const float* x0  = (const float*)d_in[0];
    const float* x1  = (const float*)d_in[1];
    const float* x2  = (const float*)d_in[2];
    const float* gtb = (const float*)d_in[3];
    const int*   gtl = (const int*)  d_in[4];
    float* out = (float*)d_out;

    cudaMemsetAsync(out, 0, sizeof(float));
    dim3 grid(21, BS);
    yolo_loss_kernel<<<grid, 256>>>(x0, x1, x2, gtb, gtl, out);
}

// round 9
// speedup vs baseline: 1.2217x; 1.1375x over previous
#include <cuda_runtime.h>
#include <math.h>

#define T 20
#define NC 80
#define BS 32
#define FULL 0xffffffffu

__constant__ float c_anch[3][3][2] = {
    {{116.f, 90.f}, {156.f, 198.f}, {373.f, 326.f}},
    {{ 30.f, 61.f}, { 62.f,  45.f}, { 59.f, 119.f}},
    {{ 10.f, 13.f}, { 16.f,  30.f}, { 33.f,  23.f}}
};

__device__ __forceinline__ float tanh_ap(float x) {
    float r; asm("tanh.approx.f32 %0, %1;" : "=f"(r) : "f"(x)); return r;
}
// stable softplus, fast intrinsics
__device__ __forceinline__ float sp(float z) {
    return fmaxf(z, 0.f) + __logf(1.f + __expf(-fabsf(z)));
}

template<int LVL, int W, int HW>
__device__ __forceinline__ void level_body(
    float* wred, int nblk, int b,
    const float* __restrict__ x,
    const float* __restrict__ gtb,
    const int*   __restrict__ gtl,
    float* __restrict__ out)
{
    constexpr int   N      = 3 * HW;
    constexpr float stride = (LVL == 0) ? 32.f : (LVL == 1) ? 16.f : 8.f;
    constexpr float inv_s  = 1.f / stride;   // exact power-of-two scale
    const int tid  = threadIdx.x;
    const int lane = tid & 31;
    const int wrp  = tid >> 5;

    float sax[3], say[3];
#pragma unroll
    for (int a = 0; a < 3; a++) {
        sax[a] = c_anch[LVL][a][0] * inv_s;
        say[a] = c_anch[LVL][a][1] * inv_s;
    }

    const int base = nblk * 512;
    const int n0 = base + tid;
    const int n1 = base + 256 + tid;
    const bool act0 = (n0 < N);
    const bool act1 = (n1 < N);
    const int ncl0 = act0 ? n0 : (N - 1);
    const int ncl1 = act1 ? n1 : (N - 1);

    // ---- addressing (compile-time magic div) + early global loads ----
    int a0   = ncl0 / HW;
    int rem0 = ncl0 - a0 * HW;
    int j0   = rem0 / W;
    int i0   = rem0 - j0 * W;
    const int off0 = a0 * (85 * HW) + rem0;
    int a1   = ncl1 / HW;
    int rem1 = ncl1 - a1 * HW;
    int j1   = rem1 / W;
    int i1   = rem1 - j1 * W;
    const int off1 = a1 * (85 * HW) + rem1;
    const size_t base_b = (size_t)b * 255 * HW;

    float zx0=0,zy0=0,zw0=0,zh0=0,zc0=0, zx1=0,zy1=0,zw1=0,zh1=0,zc1=0;
    if (act0) {
        const float* xp = x + base_b + off0;
        zx0 = xp[0]; zy0 = xp[HW]; zw0 = xp[2*HW]; zh0 = xp[3*HW]; zc0 = xp[4*HW];
    }
    if (act1) {
        const float* xp = x + base_b + off1;
        zx1 = xp[0]; zy1 = xp[HW]; zw1 = xp[2*HW]; zh1 = xp[3*HW]; zc1 = xp[4*HW];
    }

    // ---- lane-parallel target records (lane t owns target t; no shared, no barrier) ----
    float4 tb = make_float4(-1e30f, -1e30f, -1e30f, -1e30f);  // grid-unit box; sentinel fails screen
    float  aeps  = 1e30f;
    int    myflat = -1;
    int    labwin = 0;          // label | (win << 8)
    float4 mytgt = make_float4(0.f, 0.f, 0.f, 0.f);

    if (lane < T) {
        float4 gv = __ldg((const float4*)gtb + b * T + lane);
        bool valid = (gv.x != -1.f) || (gv.y != -1.f) || (gv.z != -1.f) || (gv.w != -1.f);
        if (valid) {
            tb.x = gv.x * inv_s; tb.y = gv.y * inv_s;
            tb.z = gv.z * inv_s; tb.w = gv.w * inv_s;
            float gw = tb.z - tb.x, gh = tb.w - tb.y;   // exact: pow2 scaling distributes
            aeps = gw * gh + 1e-16f;
            float gxc = (tb.x + tb.z) * 0.5f;
            float gyc = (tb.y + tb.w) * 0.5f;
            int gi = min(max((int)gxc, 0), W - 1);
            int gj = min(max((int)gyc, 0), W - 1);

            int best = 0; float bi = -1.f;
#pragma unroll
            for (int a = 0; a < 3; a++) {
                float inter = fminf(gw, sax[a]) * fminf(gh, say[a]);
                float u = gw * gh + sax[a] * say[a] - inter + 1e-16f;
                float io = inter / u;
                if (io > bi) { bi = io; best = a; }
            }
            myflat = best * HW + gj * W + gi;
            float bsx = (best == 0) ? sax[0] : (best == 1) ? sax[1] : sax[2];
            float bsy = (best == 0) ? say[0] : (best == 1) ? say[1] : say[2];
            mytgt = make_float4(gxc - (float)gi, gyc - (float)gj,
                                __logf(gw / bsx + 1e-16f),
                                __logf(gh / bsy + 1e-16f));
            labwin = min(max(__ldg(gtl + b * T + lane), 0), NC - 1);
        }
    }
    // last-writer-wins: winner of each flat-group = highest lane in match group
    {
        unsigned key = (myflat >= 0) ? (unsigned)myflat : (0x80000000u | lane);
        unsigned mm  = __match_any_sync(FULL, key);
        bool win = (myflat >= 0) && ((31 - __clz(mm)) == lane);
        labwin |= win ? 0x100 : 0;
    }

    // ---- warp windows + target screen (necessary condition for IoU>0.5 AND for positives) ----
    int imin0 = __reduce_min_sync(FULL, i0), imax0 = __reduce_max_sync(FULL, i0);
    int jmin0 = __reduce_min_sync(FULL, j0), jmax0 = __reduce_max_sync(FULL, j0);
    int imin1 = __reduce_min_sync(FULL, i1), imax1 = __reduce_max_sync(FULL, i1);
    int jmin1 = __reduce_min_sync(FULL, j1), jmax1 = __reduce_max_sync(FULL, j1);
    bool ov0 = (tb.x <= (float)(imax0 + 1)) && (tb.z >= (float)imin0)
            && (tb.y <= (float)(jmax0 + 1)) && (tb.w >= (float)jmin0);
    bool ov1 = (tb.x <= (float)(imax1 + 1)) && (tb.z >= (float)imin1)
            && (tb.y <= (float)(jmax1 + 1)) && (tb.w >= (float)jmin1);
    const unsigned mask0 = __ballot_sync(FULL, ov0);
    const unsigned mask1 = __ballot_sync(FULL, ov1);

    // ---- pruned masked loop per cell: ignore test + positive detection + labels ----
    int Lig0 = -1, Lp0 = -1, Lig1 = -1, Lp1 = -1;
    unsigned m0a=0, m1a=0, m2a=0, m0b=0, m1b=0, m2b=0;

    if (mask0) {   // warp-uniform
        float sx = 0.5f * tanh_ap(0.5f * zx0) + 0.5f;
        float sy = 0.5f * tanh_ap(0.5f * zy0) + 0.5f;
        float cx = sx + (float)i0, cy = sy + (float)j0;
        float sxa = (a0 == 0) ? sax[0] : (a0 == 1) ? sax[1] : sax[2];
        float sya = (a0 == 0) ? say[0] : (a0 == 1) ? say[1] : say[2];
        float bw = __expf(zw0) * sxa, bh = __expf(zh0) * sya;
        float px1 = cx - 0.5f*bw, py1 = cy - 0.5f*bh;
        float px2 = cx + 0.5f*bw, py2 = cy + 0.5f*bh;
        float ap  = act0 ? (bw * bh) : 1e30f;
        unsigned m = mask0;
        do {
            int t = __ffs(m) - 1; m &= m - 1;
            float bx1t = __shfl_sync(FULL, tb.x, t);
            float by1t = __shfl_sync(FULL, tb.y, t);
            float bx2t = __shfl_sync(FULL, tb.z, t);
            float by2t = __shfl_sync(FULL, tb.w, t);
            float ae   = __shfl_sync(FULL, aeps, t);
            int   ft   = __shfl_sync(FULL, myflat, t);
            int   lw   = __shfl_sync(FULL, labwin, t);
            float iw = fminf(px2, bx2t) - fmaxf(px1, bx1t);
            float ih = fminf(py2, by2t) - fmaxf(py1, by1t);
            float in_ = fmaxf(iw, 0.f) * fmaxf(ih, 0.f);
            if (fmaf(3.f, in_, -ap) > ae) Lig0 = t;      // ascending: last = max t
            if (ft == n0) {
                int l = lw & 0xff;
                if (l < 32) m0a |= 1u << l; else if (l < 64) m1a |= 1u << (l-32); else m2a |= 1u << (l-64);
                if (lw & 0x100) Lp0 = t;
            }
        } while (m);
    }
    if (mask1) {
        float sx = 0.5f * tanh_ap(0.5f * zx1) + 0.5f;
        float sy = 0.5f * tanh_ap(0.5f * zy1) + 0.5f;
        float cx = sx + (float)i1, cy = sy + (float)j1;
        float sxa = (a1 == 0) ? sax[0] : (a1 == 1) ? sax[1] : sax[2];
        float sya = (a1 == 0) ? say[0] : (a1 == 1) ? say[1] : say[2];
        float bw = __expf(zw1) * sxa, bh = __expf(zh1) * sya;
        float px1 = cx - 0.5f*bw, py1 = cy - 0.5f*bh;
        float px2 = cx + 0.5f*bw, py2 = cy + 0.5f*bh;
        float ap  = act1 ? (bw * bh) : 1e30f;
        unsigned m = mask1;
        do {
            int t = __ffs(m) - 1; m &= m - 1;
            float bx1t = __shfl_sync(FULL, tb.x, t);
            float by1t = __shfl_sync(FULL, tb.y, t);
            float bx2t = __shfl_sync(FULL, tb.z, t);
            float by2t = __shfl_sync(FULL, tb.w, t);
            float ae   = __shfl_sync(FULL, aeps, t);
            int   ft   = __shfl_sync(FULL, myflat, t);
            int   lw   = __shfl_sync(FULL, labwin, t);
            float iw = fminf(px2, bx2t) - fmaxf(px1, bx1t);
            float ih = fminf(py2, by2t) - fmaxf(py1, by1t);
            float in_ = fmaxf(iw, 0.f) * fmaxf(ih, 0.f);
            if (fmaf(3.f, in_, -ap) > ae) Lig1 = t;
            if (ft == n1) {
                int l = lw & 0xff;
                if (l < 32) m0b |= 1u << l; else if (l < 64) m1b |= 1u << (l-32); else m2b |= 1u << (l-64);
                if (lw & 0x100) Lp1 = t;
            }
        } while (m);
    }

    const bool pos0 = act0 && (Lp0 >= 0) && (Lp0 >= Lig0);
    const bool pos1 = act1 && (Lp1 >= 0) && (Lp1 >= Lig1);
    const bool neg0 = act0 && (Lig0 < 0) && !pos0;
    const bool neg1 = act1 && (Lig1 < 0) && !pos1;

    // winner targets via per-lane shfl (clamped src; executed non-divergently)
    int s0 = max(Lp0, 0), s1 = max(Lp1, 0);
    float tgx0 = __shfl_sync(FULL, mytgt.x, s0), tgy0 = __shfl_sync(FULL, mytgt.y, s0);
    float tgw0 = __shfl_sync(FULL, mytgt.z, s0), tgh0 = __shfl_sync(FULL, mytgt.w, s0);
    float tgx1 = __shfl_sync(FULL, mytgt.x, s1), tgy1 = __shfl_sync(FULL, mytgt.y, s1);
    float tgw1 = __shfl_sync(FULL, mytgt.z, s1), tgh1 = __shfl_sync(FULL, mytgt.w, s1);

    // ---- loss assembly ----
    // batched negative conf: sp(z) = max(z,0) + log1p(e^-|z|); product the log1p args
    float e0 = __expf(-fabsf(zc0));
    float e1 = __expf(-fabsf(zc1));
    float tprod = (neg0 ? (1.f + e0) : 1.f) * (neg1 ? (1.f + e1) : 1.f);
    float bacc  = (neg0 ? fmaxf(zc0, 0.f) : 0.f) + (neg1 ? fmaxf(zc1, 0.f) : 0.f);
    float loss = bacc + __logf(tprod);

    if (pos0) {
        float bxl = tgx0 * sp(-zx0) + (1.f - tgx0) * sp(zx0);
        float byl = tgy0 * sp(-zy0) + (1.f - tgy0) * sp(zy0);
        float dw = zw0 - tgw0, dh = zh0 - tgh0;
        loss += 2.5f * (bxl + byl + dw*dw + dh*dh) + sp(-zc0);
    }
    if (pos1) {
        float bxl = tgx1 * sp(-zx1) + (1.f - tgx1) * sp(zx1);
        float byl = tgy1 * sp(-zy1) + (1.f - tgy1) * sp(zy1);
        float dw = zw1 - tgw1, dh = zh1 - tgh1;
        loss += 2.5f * (bxl + byl + dw*dw + dh*dh) + sp(-zc1);
    }

    // ---- warp-cooperative class loss (rare positives) ----
    // BCE(sig(z),1) = sp(z) - z ; BCE(sig(z),0) = sp(z)
#pragma unroll
    for (int c = 0; c < 2; c++) {
        bool p       = c ? pos1 : pos0;
        int  off     = c ? off1 : off0;
        unsigned M0t = c ? m0b : m0a, M1t = c ? m1b : m1a, M2t = c ? m2b : m2a;
        unsigned bal = __ballot_sync(FULL, p);
        while (bal) {
            int src = __ffs(bal) - 1;
            bal &= bal - 1;
            int offs    = __shfl_sync(FULL, off, src);
            unsigned M0 = __shfl_sync(FULL, M0t, src);
            unsigned M1 = __shfl_sync(FULL, M1t, src);
            unsigned M2 = __shfl_sync(FULL, M2t, src);
            const float* cps = x + base_b + offs + (size_t)5 * HW;
            float z = __ldg(cps + (size_t)lane * HW);
            float acc = sp(z) - (((M0 >> lane) & 1u) ? z : 0.f);
            z = __ldg(cps + (size_t)(lane + 32) * HW);
            acc += sp(z) - (((M1 >> lane) & 1u) ? z : 0.f);
            if (lane < 16) {
                z = __ldg(cps + (size_t)(lane + 64) * HW);
                acc += sp(z) - (((M2 >> lane) & 1u) ? z : 0.f);
            }
            loss += acc;
        }
    }

    // ---- reduction (only barrier in the kernel) ----
#pragma unroll
    for (int o = 16; o > 0; o >>= 1)
        loss += __shfl_down_sync(FULL, loss, o);
    if (lane == 0) wred[wrp] = loss;
    __syncthreads();
    if (wrp == 0) {
        float v = (lane < 8) ? wred[lane] : 0.f;
#pragma unroll
        for (int o = 4; o > 0; o >>= 1)
            v += __shfl_down_sync(FULL, v, o);
        if (lane == 0) atomicAdd(out, v * (1.f / (float)BS));
    }
}

// grid: (21, 32). bx==0 -> lvl0; [1,5) -> lvl1; [5,21) -> lvl2.
// 256 threads x 2 strided cells = 512 cells/block; no shared target phase.
__global__ __launch_bounds__(256)
void yolo_loss_kernel(const float* __restrict__ x0,
                      const float* __restrict__ x1,
                      const float* __restrict__ x2,
                      const float* __restrict__ gtb,
                      const int*   __restrict__ gtl,
                      float* __restrict__ out)
{
    __shared__ float wred[8];
    const int bx = blockIdx.x;
    const int b  = blockIdx.y;
    if (bx == 0)      level_body<0, 13, 169 >(wred, 0,      b, x0, gtb, gtl, out);
    else if (bx < 5)  level_body<1, 26, 676 >(wred, bx - 1, b, x1, gtb, gtl, out);
    else              level_body<2, 52, 2704>(wred, bx - 5, b, x2, gtb, gtl, out);
}

extern "C" void kernel_launch(void* const* d_in, const int* in_sizes, int n_in,
                              void* d_out, int out_size)
{
    const float* x0  = (const float*)d_in[0];
    const float* x1  = (const float*)d_in[1];
    const float* x2  = (const float*)d_in[2];
    const float* gtb = (const float*)d_in[3];
    const int*   gtl = (const int*)  d_in[4];
    float* out = (float*)d_out;

    cudaMemsetAsync(out, 0, sizeof(float));
    dim3 grid(21, BS);
    yolo_loss_kernel<<<grid, 256>>>(x0, x1, x2, gtb, gtl, out);
}